// round 1
// baseline (speedup 1.0000x reference)
#include <cuda_runtime.h>
#include <cstdint>

#define B_   256
#define D_   784
#define H_   1024
#define T_   10
#define NCH  18
#define CHLEN 44
#define BT   32

// ---------------- scratch (static device arrays; no allocs) ----------------
__device__ float g_Wt[D_ * H_];          // W transposed: [D][H]
__device__ float g_xt[D_ * B_];          // x transposed + float: [D][B]
__device__ float g_Vt[D_ * T_ * H_];     // V transposed per step: [D][T][H]
__device__ float g_Apre[NCH * B_ * H_];  // chunk-start accumulators

// ---------------- helpers ----------------
__device__ __forceinline__ float ex2f(float x) {
    float y; asm("ex2.approx.f32 %0, %1;" : "=f"(y) : "f"(x)); return y;
}
__device__ __forceinline__ float rcpf(float x) {
    float y; asm("rcp.approx.f32 %0, %1;" : "=f"(y) : "f"(x)); return y;
}
__device__ __forceinline__ float sigmoidf_(float x) {
    // 1 / (1 + exp(-x)) = 1 / (1 + 2^(-x*log2e))
    return rcpf(1.0f + ex2f(x * -1.4426950408889634f));
}
__device__ __forceinline__ void cp_async16(float* s, const float* g) {
    unsigned sa = (unsigned)__cvta_generic_to_shared(s);
    asm volatile("cp.async.ca.shared.global [%0], [%1], 16;\n" :: "r"(sa), "l"(g));
}
__device__ __forceinline__ void cp_async8(float* s, const float* g) {
    unsigned sa = (unsigned)__cvta_generic_to_shared(s);
    asm volatile("cp.async.ca.shared.global [%0], [%1], 8;\n" :: "r"(sa), "l"(g));
}
__device__ __forceinline__ void cp_commit() {
    asm volatile("cp.async.commit_group;\n" ::: "memory");
}

// ---------------- K1a: transpose W [H][D] -> Wt [D][H] ----------------
__global__ void k_transW(const float* __restrict__ W) {
    __shared__ float tile[32][33];
    int d = blockIdx.x * 32 + threadIdx.x;
    int h = blockIdx.y * 32 + threadIdx.y;
#pragma unroll
    for (int j = 0; j < 32; j += 8)
        if (d < D_) tile[threadIdx.y + j][threadIdx.x] = W[(h + j) * D_ + d];
    __syncthreads();
    int ho = blockIdx.y * 32 + threadIdx.x;
    int do_ = blockIdx.x * 32 + threadIdx.y;
#pragma unroll
    for (int j = 0; j < 32; j += 8)
        if (do_ + j < D_) g_Wt[(do_ + j) * H_ + ho] = tile[threadIdx.x][threadIdx.y + j];
}

// ---------------- K1b: transpose x [B][D] int -> xt [D][B] float ----------------
__global__ void k_transX(const int* __restrict__ x) {
    int idx = blockIdx.x * 256 + threadIdx.x;   // grid covers B_*D_
    int b = idx / D_;
    int d = idx - b * D_;
    g_xt[d * B_ + b] = (float)x[idx];
}

// ---------------- K1c: transpose V [D][H][T] -> Vt [D][T][H] ----------------
__global__ void k_transV(const float* __restrict__ V) {
    int d = blockIdx.x >> 2;
    int h = ((blockIdx.x & 3) << 8) | threadIdx.x;
    const float2* src = (const float2*)(V + (size_t)(d * H_ + h) * T_);
    float2 v[5];
#pragma unroll
    for (int q = 0; q < 5; q++) v[q] = src[q];
    const float* vf = (const float*)v;
#pragma unroll
    for (int t = 0; t < T_; t++)
        g_Vt[(size_t)d * (T_ * H_) + t * H_ + h] = vf[t];
}

// ---------------- K2: chunk sums S_k[b,h] into g_Apre slots ----------------
__global__ __launch_bounds__(256) void k_chunksum() {
    int bg = blockIdx.x;        // 0..7  (32 batches each)
    int k  = blockIdx.y;        // 0..NCH-1
    int i0 = k * CHLEN;
    int len = min(CHLEN, D_ - i0);
    __shared__ float xs2[CHLEN * 32];
    int tid = threadIdx.x;
    for (int idx = tid; idx < len * 32; idx += 256) {
        int j = idx >> 5, b = idx & 31;
        xs2[idx] = g_xt[(i0 + j) * B_ + bg * 32 + b];
    }
    __syncthreads();
    int h0 = tid * 4;
    float4 acc[32];
#pragma unroll
    for (int b = 0; b < 32; b++) acc[b] = make_float4(0.f, 0.f, 0.f, 0.f);
    for (int j = 0; j < len; j++) {
        float4 wv = *(const float4*)&g_Wt[(i0 + j) * H_ + h0];
        const float* xr = &xs2[j * 32];
#pragma unroll
        for (int b = 0; b < 32; b++) {
            float xb = xr[b];
            acc[b].x = fmaf(xb, wv.x, acc[b].x);
            acc[b].y = fmaf(xb, wv.y, acc[b].y);
            acc[b].z = fmaf(xb, wv.z, acc[b].z);
            acc[b].w = fmaf(xb, wv.w, acc[b].w);
        }
    }
#pragma unroll
    for (int b = 0; b < 32; b++)
        *(float4*)&g_Apre[(size_t)(k * B_ + bg * 32 + b) * H_ + h0] = acc[b];
}

// ---------------- K3: exclusive prefix over chunks (+c), in place ----------------
__global__ void k_prefix(const float* __restrict__ c) {
    int idx = blockIdx.x * 256 + threadIdx.x;   // B_*H_/4 threads
    int b  = idx >> 8;
    int h0 = (idx & 255) * 4;
    float4 acc = *(const float4*)&c[h0];
#pragma unroll
    for (int k = 0; k < NCH; k++) {
        float4* p = (float4*)&g_Apre[(size_t)(k * B_ + b) * H_ + h0];
        float4 s = *p;
        *p = acc;
        acc.x += s.x; acc.y += s.y; acc.z += s.z; acc.w += s.w;
    }
}

// ---------------- K4: main fused kernel ----------------
// smem layout (floats):
//   a_s : 32*1024            = 32768
//   Vs  : 2 * 10*1024        = 20480
//   ws  : 2 * 1024           =  2048
//   xs  : 2 * 32             =    64
//   bs  : 2 * 16             =    32
#define SM_A  0
#define SM_V  32768
#define SM_W  (32768 + 20480)
#define SM_X  (SM_W + 2048)
#define SM_B  (SM_X + 64)
#define SM_FLOATS (SM_B + 32)

__device__ __forceinline__ void stage(float* sm, int i, int pb, int tile, int tid,
                                      const float* __restrict__ bias) {
    // V row: 10240 floats = 2560 x 16B
    const float* vg = g_Vt + (size_t)i * (T_ * H_);
    float* vs = sm + SM_V + pb * (T_ * H_);
#pragma unroll
    for (int q = 0; q < 10; q++)
        cp_async16(vs + (tid + q * 256) * 4, vg + (tid + q * 256) * 4);
    // W row: 1024 floats
    cp_async16(sm + SM_W + pb * H_ + tid * 4, g_Wt + (size_t)i * H_ + tid * 4);
    // x slice: 32 floats
    if (tid < 8)
        cp_async16(sm + SM_X + pb * 32 + tid * 4, g_xt + (size_t)i * B_ + tile * 32 + tid * 4);
    // bias row: 10 floats (8B chunks)
    if (tid < 5)
        cp_async8(sm + SM_B + pb * 16 + tid * 2, bias + (size_t)i * T_ + tid * 2);
}

__global__ __launch_bounds__(256) void k_main(const float* __restrict__ bias,
                                              float* __restrict__ out) {
    extern __shared__ float sm[];
    const int tid   = threadIdx.x;
    const int w     = tid >> 5;
    const int L     = tid & 31;
    const int tile  = blockIdx.x;   // 0..7
    const int chunk = blockIdx.y;   // 0..NCH-1
    const int i0  = chunk * CHLEN;
    const int len = min(CHLEN, D_ - i0);

    // load a tile (32 x 1024) from prefix scratch
    const float4* ap = (const float4*)(g_Apre + (size_t)(chunk * B_ + tile * 32) * H_);
    float4* asv = (float4*)(sm + SM_A);
#pragma unroll
    for (int q = 0; q < 32; q++) asv[tid + q * 256] = ap[tid + q * 256];

    stage(sm, i0, 0, tile, tid, bias); cp_commit();
    stage(sm, i0 + 1, 1, tile, tid, bias); cp_commit();

    const int bbase = w * 4;
    float* aRow0 = sm + SM_A + (bbase + 0) * H_;
    float* aRow1 = sm + SM_A + (bbase + 1) * H_;
    float* aRow2 = sm + SM_A + (bbase + 2) * H_;
    float* aRow3 = sm + SM_A + (bbase + 3) * H_;

    for (int s = 0; s < len; s++) {
        const int i  = i0 + s;
        const int pb = s & 1;
        if (s + 1 < len) asm volatile("cp.async.wait_group 1;\n" ::: "memory");
        else             asm volatile("cp.async.wait_group 0;\n" ::: "memory");
        __syncthreads();

        const float* Vp = sm + SM_V + pb * (T_ * H_);
        const float* Wp = sm + SM_W + pb * H_;
        const float xv0 = sm[SM_X + pb * 32 + bbase + 0];
        const float xv1 = sm[SM_X + pb * 32 + bbase + 1];
        const float xv2 = sm[SM_X + pb * 32 + bbase + 2];
        const float xv3 = sm[SM_X + pb * 32 + bbase + 3];

        float acc[4][10];
#pragma unroll
        for (int k = 0; k < 4; k++)
#pragma unroll
            for (int t = 0; t < T_; t++) acc[k][t] = 0.f;

#pragma unroll 4
        for (int j = 0; j < 32; j++) {
            const int h = L + j * 32;
            const float wv = Wp[h];
            float a0 = aRow0[h], a1 = aRow1[h], a2 = aRow2[h], a3 = aRow3[h];
            const float s0 = sigmoidf_(a0);
            const float s1 = sigmoidf_(a1);
            const float s2 = sigmoidf_(a2);
            const float s3 = sigmoidf_(a3);
            aRow0[h] = fmaf(xv0, wv, a0);
            aRow1[h] = fmaf(xv1, wv, a1);
            aRow2[h] = fmaf(xv2, wv, a2);
            aRow3[h] = fmaf(xv3, wv, a3);
#pragma unroll
            for (int t = 0; t < T_; t++) {
                const float vv = Vp[t * H_ + h];
                acc[0][t] = fmaf(s0, vv, acc[0][t]);
                acc[1][t] = fmaf(s1, vv, acc[1][t]);
                acc[2][t] = fmaf(s2, vv, acc[2][t]);
                acc[3][t] = fmaf(s3, vv, acc[3][t]);
            }
        }

        // full-warp reduction (lanes span h)
#pragma unroll
        for (int k = 0; k < 4; k++)
#pragma unroll
            for (int t = 0; t < T_; t++)
#pragma unroll
                for (int m = 16; m > 0; m >>= 1)
                    acc[k][t] += __shfl_xor_sync(0xffffffffu, acc[k][t], m);

        if (L < 4) {
            float l[10];
#pragma unroll
            for (int t = 0; t < T_; t++) l[t] = acc[L][t] + sm[SM_B + pb * 16 + t];
            float mx = l[0];
#pragma unroll
            for (int t = 1; t < T_; t++) mx = fmaxf(mx, l[t]);
            float e[10]; float sum = 0.f;
#pragma unroll
            for (int t = 0; t < T_; t++) {
                e[t] = ex2f((l[t] - mx) * 1.4426950408889634f);
                sum += e[t];
            }
            const float r = rcpf(sum);
            const int b = tile * 32 + bbase + L;
            float* op = out + (size_t)b * (T_ * D_) + i;
#pragma unroll
            for (int t = 0; t < T_; t++) op[t * D_] = e[t] * r;
        }

        __syncthreads();   // all reads of buffer pb done before refill
        if (s + 2 < len) { stage(sm, i0 + s + 2, pb, tile, tid, bias); cp_commit(); }
    }
}

// ---------------- launch ----------------
extern "C" void kernel_launch(void* const* d_in, const int* in_sizes, int n_in,
                              void* d_out, int out_size) {
    const int*   x    = (const int*)d_in[0];     // [256,784] int32
    const float* W    = (const float*)d_in[1];   // [1024,784]
    const float* c    = (const float*)d_in[2];   // [1024,1]
    const float* V    = (const float*)d_in[3];   // [784,1024,10]
    const float* bias = (const float*)d_in[4];   // [784,10]
    float* out = (float*)d_out;                  // [256,10,784]

    static_assert(SM_FLOATS * 4 <= 232448, "smem budget");
    cudaFuncSetAttribute(k_main, cudaFuncAttributeMaxDynamicSharedMemorySize,
                         SM_FLOATS * (int)sizeof(float));

    k_transW<<<dim3((D_ + 31) / 32, H_ / 32), dim3(32, 8)>>>(W);
    k_transX<<<(B_ * D_) / 256, 256>>>(x);
    k_transV<<<D_ * (H_ / 256), 256>>>(V);
    k_chunksum<<<dim3(B_ / BT, NCH), 256>>>();
    k_prefix<<<(B_ * H_ / 4) / 256, 256>>>(c);
    k_main<<<dim3(B_ / BT, NCH), 256, SM_FLOATS * (int)sizeof(float)>>>(bias, out);
}

// round 2
// speedup vs baseline: 1.6577x; 1.6577x over previous
#include <cuda_runtime.h>
#include <cstdint>

#define B_   256
#define D_   784
#define H_   1024
#define T_   10
#define NCH  18
#define CHLEN 44

typedef unsigned long long ull;

// ---------------- scratch ----------------
__device__ __align__(16) float g_Wt[D_ * H_];          // W transposed: [D][H]
__device__ __align__(16) float g_xt[D_ * B_];          // x transposed float: [D][B]
__device__ __align__(16) float g_Vt[D_ * T_ * H_];     // V transposed: [D][T][H]
__device__ __align__(16) float g_Apre[NCH * B_ * H_];  // chunk-start accumulators [k][b][h]

// ---------------- helpers ----------------
__device__ __forceinline__ float ex2f(float x) {
    float y; asm("ex2.approx.f32 %0, %1;" : "=f"(y) : "f"(x)); return y;
}
__device__ __forceinline__ float rcpf(float x) {
    float y; asm("rcp.approx.f32 %0, %1;" : "=f"(y) : "f"(x)); return y;
}
__device__ __forceinline__ ull fma2_(ull a, ull b, ull c) {
    ull d; asm("fma.rn.f32x2 %0, %1, %2, %3;" : "=l"(d) : "l"(a), "l"(b), "l"(c)); return d;
}
__device__ __forceinline__ ull mul2_(ull a, ull b) {
    ull d; asm("mul.rn.f32x2 %0, %1, %2;" : "=l"(d) : "l"(a), "l"(b)); return d;
}
__device__ __forceinline__ ull pack2_(float lo, float hi) {
    ull d; asm("mov.b64 %0, {%1, %2};" : "=l"(d) : "f"(lo), "f"(hi)); return d;
}
__device__ __forceinline__ void unpack2_(ull v, float& lo, float& hi) {
    asm("mov.b64 {%0, %1}, %2;" : "=f"(lo), "=f"(hi) : "l"(v));
}
__device__ __forceinline__ void cp_async16(float* s, const float* g) {
    unsigned sa = (unsigned)__cvta_generic_to_shared(s);
    asm volatile("cp.async.ca.shared.global [%0], [%1], 16;\n" :: "r"(sa), "l"(g));
}
__device__ __forceinline__ void cp_async8(float* s, const float* g) {
    unsigned sa = (unsigned)__cvta_generic_to_shared(s);
    asm volatile("cp.async.ca.shared.global [%0], [%1], 8;\n" :: "r"(sa), "l"(g));
}
__device__ __forceinline__ void cp_commit() {
    asm volatile("cp.async.commit_group;\n" ::: "memory");
}

// ---------------- K1a: transpose W [H][D] -> Wt [D][H] ----------------
__global__ void k_transW(const float* __restrict__ W) {
    __shared__ float tile[32][33];
    int d = blockIdx.x * 32 + threadIdx.x;
    int h = blockIdx.y * 32 + threadIdx.y;
#pragma unroll
    for (int j = 0; j < 32; j += 8)
        if (d < D_) tile[threadIdx.y + j][threadIdx.x] = W[(h + j) * D_ + d];
    __syncthreads();
    int ho = blockIdx.y * 32 + threadIdx.x;
    int do_ = blockIdx.x * 32 + threadIdx.y;
#pragma unroll
    for (int j = 0; j < 32; j += 8)
        if (do_ + j < D_) g_Wt[(do_ + j) * H_ + ho] = tile[threadIdx.x][threadIdx.y + j];
}

// ---------------- K1b: transpose x [B][D] int -> xt [D][B] float ----------------
__global__ void k_transX(const int* __restrict__ x) {
    int idx = blockIdx.x * 256 + threadIdx.x;
    int b = idx / D_;
    int d = idx - b * D_;
    g_xt[d * B_ + b] = (float)x[idx];
}

// ---------------- K1c: transpose V [D][H][T] -> Vt [D][T][H] ----------------
__global__ void k_transV(const float* __restrict__ V) {
    int d = blockIdx.x >> 2;
    int h = ((blockIdx.x & 3) << 8) | threadIdx.x;
    const float2* src = (const float2*)(V + (size_t)(d * H_ + h) * T_);
    float2 v[5];
#pragma unroll
    for (int q = 0; q < 5; q++) v[q] = src[q];
    const float* vf = (const float*)v;
#pragma unroll
    for (int t = 0; t < T_; t++)
        g_Vt[(size_t)d * (T_ * H_) + t * H_ + h] = vf[t];
}

// ---------------- K2: chunk sums S_k[b,h], with prefetch ----------------
__global__ __launch_bounds__(256) void k_chunksum() {
    int bg = blockIdx.x;        // 0..7
    int k  = blockIdx.y;        // 0..NCH-1
    int i0 = k * CHLEN;
    int len = min(CHLEN, D_ - i0);
    __shared__ float xs2[CHLEN * 32];
    int tid = threadIdx.x;
    for (int idx = tid; idx < len * 32; idx += 256) {
        int j = idx >> 5, b = idx & 31;
        xs2[idx] = g_xt[(i0 + j) * B_ + bg * 32 + b];
    }
    __syncthreads();
    int h0 = tid * 4;
    float4 acc[32];
#pragma unroll
    for (int b = 0; b < 32; b++) acc[b] = make_float4(0.f, 0.f, 0.f, 0.f);
    float4 wn = *(const float4*)&g_Wt[i0 * H_ + h0];
    for (int j = 0; j < len; j++) {
        float4 wv = wn;
        if (j + 1 < len) wn = *(const float4*)&g_Wt[(i0 + j + 1) * H_ + h0];
        const float* xr = &xs2[j * 32];
#pragma unroll
        for (int b = 0; b < 32; b++) {
            float xb = xr[b];
            acc[b].x = fmaf(xb, wv.x, acc[b].x);
            acc[b].y = fmaf(xb, wv.y, acc[b].y);
            acc[b].z = fmaf(xb, wv.z, acc[b].z);
            acc[b].w = fmaf(xb, wv.w, acc[b].w);
        }
    }
#pragma unroll
    for (int b = 0; b < 32; b++)
        *(float4*)&g_Apre[(size_t)(k * B_ + bg * 32 + b) * H_ + h0] = acc[b];
}

// ---------------- K3: exclusive prefix over chunks (+c) ----------------
__global__ void k_prefix(const float* __restrict__ c) {
    int idx = blockIdx.x * 256 + threadIdx.x;
    int b  = idx >> 8;
    int h0 = (idx & 255) * 4;
    float4 acc = *(const float4*)&c[h0];
#pragma unroll
    for (int k = 0; k < NCH; k++) {
        float4* p = (float4*)&g_Apre[(size_t)(k * B_ + b) * H_ + h0];
        float4 s = *p;
        *p = acc;
        acc.x += s.x; acc.y += s.y; acc.z += s.z; acc.w += s.w;
    }
}

// ---------------- K4: main fused kernel ----------------
// smem layout (floats):
#define SM_V   0                     // 2 * 10*1024 = 20480
#define SM_W   20480                 // 2 * 1024    =  2048
#define SM_X   (SM_W + 2048)         // 2 * 32
#define SM_BB  (SM_X + 64)           // 2 * 16
#define SM_RED (SM_BB + 32)          // 8*10*32 = 2560
#define SM_LG  (SM_RED + 2560)       // 32*13   =  416
#define SM_O   (SM_LG + 416)         // 10*32*45 = 14400
#define SM_FLOATS (SM_O + 14400)     // 40000 floats = 160000 B

__device__ __forceinline__ void stage(float* sm, int i, int pb, int tile, int tid,
                                      const float* __restrict__ bias) {
    const float* vg = g_Vt + (size_t)i * (T_ * H_);
    float* vs = sm + SM_V + pb * (T_ * H_);
#pragma unroll
    for (int q = 0; q < 10; q++)
        cp_async16(vs + (tid + q * 256) * 4, vg + (tid + q * 256) * 4);
    cp_async16(sm + SM_W + pb * H_ + tid * 4, g_Wt + (size_t)i * H_ + tid * 4);
    if (tid < 8)
        cp_async16(sm + SM_X + pb * 32 + tid * 4, g_xt + (size_t)i * B_ + tile * 32 + tid * 4);
    if (tid < 5)
        cp_async8(sm + SM_BB + pb * 16 + tid * 2, bias + (size_t)i * T_ + tid * 2);
}

__global__ __launch_bounds__(256, 1) void k_main(const float* __restrict__ bias,
                                                 float* __restrict__ out) {
    extern __shared__ float sm[];
    const int tid   = threadIdx.x;
    const int w     = tid >> 5;
    const int L     = tid & 31;       // lane = batch within tile
    const int tile  = blockIdx.x;     // 0..7
    const int chunk = blockIdx.y;     // 0..NCH-1
    const int i0  = chunk * CHLEN;
    const int len = min(CHLEN, D_ - i0);
    const int h0  = w * 128;          // warp's h-slice [h0, h0+128)

    // a in registers: 128 h-values as 64 packed f32x2 pairs
    ull a2[64];
    {
        const ulonglong2* ag = (const ulonglong2*)(g_Apre +
            (size_t)(chunk * B_ + tile * 32 + L) * H_ + h0);
#pragma unroll
        for (int g = 0; g < 32; g++) {
            ulonglong2 v = ag[g];
            a2[2 * g]     = v.x;
            a2[2 * g + 1] = v.y;
        }
    }

    stage(sm, i0, 0, tile, tid, bias); cp_commit();
    if (len > 1) { stage(sm, i0 + 1, 1, tile, tid, bias); cp_commit(); }

    const ull NEG2 = pack2_(-1.4426950408889634f, -1.4426950408889634f);

    for (int s = 0; s < len; s++) {
        const int pb = s & 1;
        if (s + 1 < len) asm volatile("cp.async.wait_group 1;\n" ::: "memory");
        else             asm volatile("cp.async.wait_group 0;\n" ::: "memory");
        __syncthreads();   // sync1: staged buffers visible; scratch free

        const float* Vp = sm + SM_V + pb * (T_ * H_);
        const float* Wp = sm + SM_W + pb * H_;
        const float xv = sm[SM_X + pb * 32 + L];
        const ull x2 = pack2_(xv, xv);

        ull acc2[T_];
#pragma unroll
        for (int t = 0; t < T_; t++) acc2[t] = pack2_(0.f, 0.f);

#pragma unroll
        for (int g = 0; g < 32; g++) {
            const int h = h0 + g * 4;
            const ulonglong2 wv = *(const ulonglong2*)(Wp + h);
            const ull ap0 = a2[2 * g], ap1 = a2[2 * g + 1];
            const ull m0 = mul2_(ap0, NEG2);
            const ull m1 = mul2_(ap1, NEG2);
            float m00, m01, m10, m11;
            unpack2_(m0, m00, m01);
            unpack2_(m1, m10, m11);
            const float e00 = ex2f(m00), e01 = ex2f(m01);
            const float e10 = ex2f(m10), e11 = ex2f(m11);
            const float s00 = rcpf(1.f + e00), s01 = rcpf(1.f + e01);
            const float s10 = rcpf(1.f + e10), s11 = rcpf(1.f + e11);
            const ull s2a = pack2_(s00, s01);
            const ull s2b = pack2_(s10, s11);
            a2[2 * g]     = fma2_(x2, wv.x, ap0);
            a2[2 * g + 1] = fma2_(x2, wv.y, ap1);
#pragma unroll
            for (int t = 0; t < T_; t++) {
                const ulonglong2 vv = *(const ulonglong2*)(Vp + t * H_ + h);
                acc2[t] = fma2_(s2a, vv.x, acc2[t]);
                acc2[t] = fma2_(s2b, vv.y, acc2[t]);
            }
        }

        // fold packed partials and publish per-warp partial logits
#pragma unroll
        for (int t = 0; t < T_; t++) {
            float lo, hi;
            unpack2_(acc2[t], lo, hi);
            sm[SM_RED + (w * T_ + t) * 32 + L] = lo + hi;
        }
        __syncthreads();   // sync2: partials visible

        // cross-warp reduce: 320 (t,b) sums of 8
        for (int p = tid; p < 32 * T_; p += 256) {
            const int t = p >> 5, b = p & 31;
            float sum = sm[SM_BB + pb * 16 + t];
#pragma unroll
            for (int ww = 0; ww < 8; ww++)
                sum += sm[SM_RED + (ww * T_ + t) * 32 + b];
            sm[SM_LG + b * 13 + t] = sum;
        }
        __syncthreads();   // sync3: logits visible; bias buffer free

        if (tid < 32) {
            float l[T_];
#pragma unroll
            for (int t = 0; t < T_; t++) l[t] = sm[SM_LG + L * 13 + t];
            float mx = l[0];
#pragma unroll
            for (int t = 1; t < T_; t++) mx = fmaxf(mx, l[t]);
            float e[T_]; float sum = 0.f;
#pragma unroll
            for (int t = 0; t < T_; t++) {
                e[t] = ex2f((l[t] - mx) * 1.4426950408889634f);
                sum += e[t];
            }
            const float r = rcpf(sum);
#pragma unroll
            for (int t = 0; t < T_; t++)
                sm[SM_O + (t * 32 + L) * 45 + s] = e[t] * r;
        }

        if (s + 2 < len) { stage(sm, i0 + s + 2, pb, tile, tid, bias); cp_commit(); }
    }

    // coalesced flush of the chunk's outputs
    __syncthreads();
    const int total = 32 * T_ * len;
    for (int idx = tid; idx < total; idx += 256) {
        const int r  = idx / len;
        const int ss = idx - r * len;
        const int b  = r / T_;
        const int t  = r - b * T_;
        out[(size_t)(tile * 32 + b) * (T_ * D_) + t * D_ + i0 + ss] =
            sm[SM_O + (t * 32 + b) * 45 + ss];
    }
}

// ---------------- launch ----------------
extern "C" void kernel_launch(void* const* d_in, const int* in_sizes, int n_in,
                              void* d_out, int out_size) {
    const int*   x    = (const int*)d_in[0];
    const float* W    = (const float*)d_in[1];
    const float* c    = (const float*)d_in[2];
    const float* V    = (const float*)d_in[3];
    const float* bias = (const float*)d_in[4];
    float* out = (float*)d_out;

    static_assert(SM_FLOATS * 4 <= 232448, "smem budget");
    cudaFuncSetAttribute(k_main, cudaFuncAttributeMaxDynamicSharedMemorySize,
                         SM_FLOATS * (int)sizeof(float));

    k_transW<<<dim3((D_ + 31) / 32, H_ / 32), dim3(32, 8)>>>(W);
    k_transX<<<(B_ * D_) / 256, 256>>>(x);
    k_transV<<<D_ * (H_ / 256), 256>>>(V);
    k_chunksum<<<dim3(B_ / 32, NCH), 256>>>();
    k_prefix<<<(B_ * H_ / 4) / 256, 256>>>(c);
    k_main<<<dim3(B_ / 32, NCH), 256, SM_FLOATS * (int)sizeof(float)>>>(bias, out);
}